// round 4
// baseline (speedup 1.0000x reference)
#include <cuda_runtime.h>

// Problem dims
#define Bsz 256   // batch
#define Ssz 512   // seq len
#define Isz 256   // input
#define Hsz 512   // hidden
#define BBsz 256  // backbone width
#define Osz 128   // output

#define NCTA 148  // B200 SM count; 1 CTA/SM in wave 1 -> co-resident

// Scratch (allocation-free: __device__ globals)
__device__ float g_xw[Ssz * Bsz * BBsz];     // [t][b][j] : x@Wb0_x + bb0
__device__ float g_h[Bsz * Hsz];             // hidden state
__device__ float g_z[Bsz * BBsz];            // z3 (last backbone activation)
__device__ float g_pA[8 * Bsz * BBsz];       // split-K partials (ping)
__device__ float g_pB[8 * Bsz * BBsz];       // split-K partials (pong)

// grid barrier state
__device__ unsigned g_count = 0;
__device__ volatile unsigned g_gen = 0;

__device__ __forceinline__ float fast_tanh(float x) {
    x = fminf(15.f, fmaxf(-15.f, x));
    float e = __expf(2.f * x);
    return (e - 1.f) / (e + 1.f);
}
__device__ __forceinline__ float fast_sigmoid(float x) {
    x = fminf(30.f, fmaxf(-30.f, x));
    return 1.f / (1.f + __expf(-x));
}

// Sense-reversing grid barrier. All CTAs resident (grid == 148 <= SM count).
__device__ __forceinline__ void gsync() {
    __syncthreads();
    if (threadIdx.x == 0) {
        __threadfence();                      // release my CTA's writes
        unsigned gen = g_gen;                 // read BEFORE arriving
        if (atomicAdd(&g_count, 1) == gridDim.x - 1) {
            g_count = 0;
            __threadfence();
            g_gen = gen + 1;
        } else {
            while (g_gen == gen) __nanosleep(32);
        }
        __threadfence();                      // acquire
    }
    __syncthreads();
}

// 16-FMA micro-kernel over one 32-wide k-tile.
// As is transposed [k][m], Bs is [k][n]; both rows padded to 68 floats
// (272 B = 17 x 16 B) so every float4 LDS is 16-byte aligned.
__device__ __forceinline__ void gemm_ktile(const float (*As)[68], const float (*Bs)[68],
                                           float acc[4][4], int tx, int ty) {
    #pragma unroll
    for (int kk = 0; kk < 32; kk++) {
        float4 a = *(const float4*)&As[kk][ty * 4];
        float4 b = *(const float4*)&Bs[kk][tx * 4];
        acc[0][0] += a.x * b.x; acc[0][1] += a.x * b.y; acc[0][2] += a.x * b.z; acc[0][3] += a.x * b.w;
        acc[1][0] += a.y * b.x; acc[1][1] += a.y * b.y; acc[1][2] += a.y * b.z; acc[1][3] += a.y * b.w;
        acc[2][0] += a.z * b.x; acc[2][1] += a.z * b.y; acc[2][2] += a.z * b.z; acc[2][3] += a.z * b.w;
        acc[3][0] += a.w * b.x; acc[3][1] += a.w * b.y; acc[3][2] += a.w * b.z; acc[3][3] += a.w * b.w;
    }
}

// ---------------------------------------------------------------------------
// Stage A: partials of h @ Wb0h.  M=256,N=256,K=512, split-K8 (chunk 64).
// unit u in [0,128): ks=u&7, tile=u>>3 (4x4 tiles of 64x64). Out: g_pA.
// ---------------------------------------------------------------------------
__device__ void stageA(int u, const float* __restrict__ Wb0h,
                       float (*As)[68], float (*Bs)[68]) {
    int ks = u & 7, tile = u >> 3;
    int m0 = (tile >> 2) * 64, n0 = (tile & 3) * 64;
    int tid = threadIdx.x;
    int tx = tid & 15, ty = tid >> 4;
    float acc[4][4] = {};

    for (int kt = 0; kt < 2; kt++) {
        int k0 = ks * 64 + kt * 32;
        #pragma unroll
        for (int s = tid; s < 512; s += 256) {
            int m = s >> 3, kg = (s & 7) * 4;
            float4 v = *(const float4*)&g_h[(m0 + m) * Hsz + k0 + kg];
            As[kg + 0][m] = v.x; As[kg + 1][m] = v.y;
            As[kg + 2][m] = v.z; As[kg + 3][m] = v.w;
        }
        #pragma unroll
        for (int s = tid; s < 512; s += 256) {
            int k = s >> 4, ng = (s & 15) * 4;
            *(float4*)&Bs[k][ng] = *(const float4*)&Wb0h[(k0 + k) * BBsz + n0 + ng];
        }
        __syncthreads();
        gemm_ktile((const float(*)[68])As, (const float(*)[68])Bs, acc, tx, ty);
        __syncthreads();
    }
    #pragma unroll
    for (int i = 0; i < 4; i++) {
        int m = m0 + ty * 4 + i;
        float4 v = {acc[i][0], acc[i][1], acc[i][2], acc[i][3]};
        *(float4*)&g_pA[(ks * Bsz + m) * BBsz + n0 + tx * 4] = v;
    }
}

// ---------------------------------------------------------------------------
// Mid stage: prologue reduces split-K partials of previous layer (+base) and
// applies tanh to build the activated A-tile for its own K-chunk, then GEMM.
// unit u in [0,128): ks=u&7 (chunk of 32), tile=u>>3.  K total = 256.
// ---------------------------------------------------------------------------
__device__ void pmid(int u, const float* __restrict__ base, int base2d,
                     const float* __restrict__ W,
                     const float* __restrict__ pin, float* __restrict__ pout,
                     float (*As)[68], float (*Bs)[68]) {
    int ks = u & 7, tile = u >> 3;
    int m0 = (tile >> 2) * 64, n0 = (tile & 3) * 64;
    int k0 = ks * 32;
    int tid = threadIdx.x;
    int tx = tid & 15, ty = tid >> 4;

    #pragma unroll
    for (int s = tid; s < 512; s += 256) {
        int m = s >> 3, kg = (s & 7) * 4;
        int gm = m0 + m, gk = k0 + kg;
        float4 v;
        if (base2d) v = *(const float4*)&base[gm * BBsz + gk];
        else        v = *(const float4*)&base[gk];
        #pragma unroll
        for (int p = 0; p < 8; p++) {
            float4 pv = *(const float4*)&pin[(p * Bsz + gm) * BBsz + gk];
            v.x += pv.x; v.y += pv.y; v.z += pv.z; v.w += pv.w;
        }
        As[kg + 0][m] = fast_tanh(v.x); As[kg + 1][m] = fast_tanh(v.y);
        As[kg + 2][m] = fast_tanh(v.z); As[kg + 3][m] = fast_tanh(v.w);
    }
    #pragma unroll
    for (int s = tid; s < 512; s += 256) {
        int k = s >> 4, ng = (s & 15) * 4;
        *(float4*)&Bs[k][ng] = *(const float4*)&W[(k0 + k) * BBsz + n0 + ng];
    }
    __syncthreads();

    float acc[4][4] = {};
    gemm_ktile((const float(*)[68])As, (const float(*)[68])Bs, acc, tx, ty);
    __syncthreads();

    #pragma unroll
    for (int i = 0; i < 4; i++) {
        int m = m0 + ty * 4 + i;
        float4 v = {acc[i][0], acc[i][1], acc[i][2], acc[i][3]};
        *(float4*)&pout[(ks * Bsz + m) * BBsz + n0 + tx * 4] = v;
    }
}

// ---------------------------------------------------------------------------
// r4: g_z = tanh(bias + sum_8 pin)   (65536 elems, all CTAs, float4 stride)
// ---------------------------------------------------------------------------
__device__ void r4(const float* __restrict__ bias, const float* __restrict__ pin) {
    int tid0 = blockIdx.x * 256 + threadIdx.x;
    for (int s = tid0; s < (Bsz * BBsz / 4); s += gridDim.x * 256) {
        int idx = s * 4;
        float4 v = *(const float4*)&bias[idx & (BBsz - 1)];
        #pragma unroll
        for (int p = 0; p < 8; p++) {
            float4 pv = *(const float4*)&pin[p * Bsz * BBsz + idx];
            v.x += pv.x; v.y += pv.y; v.z += pv.z; v.w += pv.w;
        }
        float4 o = {fast_tanh(v.x), fast_tanh(v.y), fast_tanh(v.z), fast_tanh(v.w)};
        *(float4*)&g_z[idx] = o;
    }
}

// ---------------------------------------------------------------------------
// Heads: fused 4-head GEMM (64 batch x 16 hcol x 4 heads, K=256) + CfC gate.
// unit u in [0,128): rt=u>>5 (m0), ht=u&31 (h0). Writes g_h.
// Ws aliases Bs memory: [4][32][17] = 2176 floats = 32*68 exactly.
// ---------------------------------------------------------------------------
__device__ void heads(int u, int t,
                      const float* __restrict__ Wff1, const float* __restrict__ Wff2,
                      const float* __restrict__ Wta,  const float* __restrict__ Wtb,
                      const float* __restrict__ bff1, const float* __restrict__ bff2,
                      const float* __restrict__ bta,  const float* __restrict__ btb,
                      const float* __restrict__ ts,
                      float (*As)[68], float (*Bs)[68]) {
    float (*Ws)[32][17] = (float (*)[32][17])Bs;
    int m0 = (u >> 5) * 64;
    int h0 = (u & 31) * 16;
    int tid = threadIdx.x;
    int tx = tid & 15, ty = tid >> 4;
    float acc[4][4] = {};
    const float* Wh[4] = {Wff1, Wff2, Wta, Wtb};

    for (int k0 = 0; k0 < BBsz; k0 += 32) {
        #pragma unroll
        for (int s = tid; s < 512; s += 256) {
            int m = s >> 3, kg = (s & 7) * 4;
            float4 v = *(const float4*)&g_z[(m0 + m) * BBsz + k0 + kg];
            As[kg + 0][m] = v.x; As[kg + 1][m] = v.y;
            As[kg + 2][m] = v.z; As[kg + 3][m] = v.w;
        }
        #pragma unroll
        for (int i = 0; i < 8; i++) {
            int slot = tid + i * 256;            // 0..2047
            int h = slot >> 9;                   // uniform per i
            int rem = slot & 511;
            int k = rem >> 4, j = rem & 15;
            Ws[h][k][j] = Wh[h][(k0 + k) * Hsz + h0 + j];
        }
        __syncthreads();
        #pragma unroll
        for (int kk = 0; kk < 32; kk++) {
            float4 a = *(const float4*)&As[kk][ty * 4];
            float w0 = Ws[0][kk][tx], w1 = Ws[1][kk][tx];
            float w2 = Ws[2][kk][tx], w3 = Ws[3][kk][tx];
            acc[0][0] += a.x * w0; acc[0][1] += a.x * w1; acc[0][2] += a.x * w2; acc[0][3] += a.x * w3;
            acc[1][0] += a.y * w0; acc[1][1] += a.y * w1; acc[1][2] += a.y * w2; acc[1][3] += a.y * w3;
            acc[2][0] += a.z * w0; acc[2][1] += a.z * w1; acc[2][2] += a.z * w2; acc[2][3] += a.z * w3;
            acc[3][0] += a.w * w0; acc[3][1] += a.w * w1; acc[3][2] += a.w * w2; acc[3][3] += a.w * w3;
        }
        __syncthreads();
    }
    int hcol = h0 + tx;
    float bf1 = bff1[hcol], bf2 = bff2[hcol], ba = bta[hcol], bb = btb[hcol];
    #pragma unroll
    for (int i = 0; i < 4; i++) {
        int b = m0 + ty * 4 + i;
        float tsv = ts[b * Ssz + t];
        float f1 = fast_tanh(acc[i][0] + bf1);
        float f2 = fast_tanh(acc[i][1] + bf2);
        float ti = fast_sigmoid((acc[i][2] + ba) * tsv + (acc[i][3] + bb));
        g_h[b * Hsz + hcol] = f1 * (1.f - ti) + ti * f2;
    }
}

// ---------------------------------------------------------------------------
// The persistent time loop: one kernel, software grid barriers.
// ---------------------------------------------------------------------------
__global__ void __launch_bounds__(256, 1)
loop_kernel(const float* __restrict__ ts,
            const float* __restrict__ Wb0h,
            const float* __restrict__ Wbs, const float* __restrict__ bbs,
            const float* __restrict__ Wff1, const float* __restrict__ bff1,
            const float* __restrict__ Wff2, const float* __restrict__ bff2,
            const float* __restrict__ Wta,  const float* __restrict__ bta,
            const float* __restrict__ Wtb,  const float* __restrict__ btb) {
    __shared__ __align__(16) float As[32][68];
    __shared__ __align__(16) float Bs[32][68];
    int bid = blockIdx.x;

    // zero hidden state
    for (int s = bid * 256 + threadIdx.x; s < Bsz * Hsz / 4; s += gridDim.x * 256) {
        float4 z = {0.f, 0.f, 0.f, 0.f};
        *(float4*)&g_h[s * 4] = z;
    }
    gsync();

    for (int t = 0; t < Ssz; t++) {
        if (bid < 128) stageA(bid, Wb0h, As, Bs);
        gsync();
        if (bid < 128) pmid(bid, g_xw + (size_t)t * Bsz * BBsz, 1,
                            Wbs, g_pA, g_pB, As, Bs);
        gsync();
        if (bid < 128) pmid(bid, bbs + 0 * BBsz, 0,
                            Wbs + 1 * BBsz * BBsz, g_pB, g_pA, As, Bs);
        gsync();
        if (bid < 128) pmid(bid, bbs + 1 * BBsz, 0,
                            Wbs + 2 * BBsz * BBsz, g_pA, g_pB, As, Bs);
        gsync();
        r4(bbs + 2 * BBsz, g_pB);
        gsync();
        if (bid < 128) heads(bid, t, Wff1, Wff2, Wta, Wtb,
                             bff1, bff2, bta, btb, ts, As, Bs);
        gsync();
    }
}

// ---------------------------------------------------------------------------
// Precompute g_xw[t][b][:] = bb0 + x[b][t][:] @ Wb0[0:I][:]  (time-parallel)
// ---------------------------------------------------------------------------
__global__ void precompute_xw_kernel(const float* __restrict__ x,
                                     const float* __restrict__ Wb0,
                                     const float* __restrict__ bb0) {
    __shared__ __align__(16) float As[32][68];
    __shared__ __align__(16) float Bs[32][68];
    int m0 = blockIdx.x * 64;
    int n0 = blockIdx.y * 64;
    int tid = threadIdx.x;
    int tx = tid & 15, ty = tid >> 4;
    float acc[4][4] = {};

    for (int k0 = 0; k0 < Isz; k0 += 32) {
        #pragma unroll
        for (int s = tid; s < 512; s += 256) {
            int m = s >> 3, kg = (s & 7) * 4;
            float4 v = *(const float4*)&x[(m0 + m) * Isz + k0 + kg];
            As[kg + 0][m] = v.x; As[kg + 1][m] = v.y;
            As[kg + 2][m] = v.z; As[kg + 3][m] = v.w;
        }
        #pragma unroll
        for (int s = tid; s < 512; s += 256) {
            int k = s >> 4, ng = (s & 15) * 4;
            *(float4*)&Bs[k][ng] = *(const float4*)&Wb0[(k0 + k) * BBsz + n0 + ng];
        }
        __syncthreads();
        gemm_ktile((const float(*)[68])As, (const float(*)[68])Bs, acc, tx, ty);
        __syncthreads();
    }
    float4 bias = *(const float4*)&bb0[n0 + tx * 4];
    #pragma unroll
    for (int i = 0; i < 4; i++) {
        int m = m0 + ty * 4 + i;       // m = b*S + t
        int t = m & (Ssz - 1);
        int b = m >> 9;
        float4 v = {acc[i][0] + bias.x, acc[i][1] + bias.y,
                    acc[i][2] + bias.z, acc[i][3] + bias.w};
        *(float4*)&g_xw[((size_t)t * Bsz + b) * BBsz + n0 + tx * 4] = v;
    }
}

// ---------------------------------------------------------------------------
// Final: out = h @ W_out + b_out   (256 x 128, K=512)
// ---------------------------------------------------------------------------
__global__ void final_kernel(const float* __restrict__ Wout,
                             const float* __restrict__ bout,
                             float* __restrict__ out) {
    __shared__ __align__(16) float As[32][68];
    __shared__ __align__(16) float Bs[32][68];
    int m0 = blockIdx.x * 64;
    int n0 = blockIdx.y * 64;
    int tid = threadIdx.x;
    int tx = tid & 15, ty = tid >> 4;
    float acc[4][4] = {};

    for (int k0 = 0; k0 < Hsz; k0 += 32) {
        #pragma unroll
        for (int s = tid; s < 512; s += 256) {
            int m = s >> 3, kg = (s & 7) * 4;
            float4 v = *(const float4*)&g_h[(m0 + m) * Hsz + k0 + kg];
            As[kg + 0][m] = v.x; As[kg + 1][m] = v.y;
            As[kg + 2][m] = v.z; As[kg + 3][m] = v.w;
        }
        #pragma unroll
        for (int s = tid; s < 512; s += 256) {
            int k = s >> 4, ng = (s & 15) * 4;
            *(float4*)&Bs[k][ng] = *(const float4*)&Wout[(k0 + k) * Osz + n0 + ng];
        }
        __syncthreads();
        gemm_ktile((const float(*)[68])As, (const float(*)[68])Bs, acc, tx, ty);
        __syncthreads();
    }
    float4 bias = *(const float4*)&bout[n0 + tx * 4];
    #pragma unroll
    for (int i = 0; i < 4; i++) {
        int m = m0 + ty * 4 + i;
        float4 v = {acc[i][0] + bias.x, acc[i][1] + bias.y,
                    acc[i][2] + bias.z, acc[i][3] + bias.w};
        *(float4*)&out[m * Osz + n0 + tx * 4] = v;
    }
}

// ---------------------------------------------------------------------------
// Host launcher: 3 graph nodes total.
// ---------------------------------------------------------------------------
extern "C" void kernel_launch(void* const* d_in, const int* in_sizes, int n_in,
                              void* d_out, int out_size) {
    const float* x    = (const float*)d_in[0];
    const float* ts   = (const float*)d_in[1];
    const float* Wb0  = (const float*)d_in[2];
    const float* bb0  = (const float*)d_in[3];
    const float* Wbs  = (const float*)d_in[4];   // (3, 256, 256)
    const float* bbs  = (const float*)d_in[5];   // (3, 256)
    const float* Wff1 = (const float*)d_in[6];
    const float* bff1 = (const float*)d_in[7];
    const float* Wff2 = (const float*)d_in[8];
    const float* bff2 = (const float*)d_in[9];
    const float* Wta  = (const float*)d_in[10];
    const float* bta  = (const float*)d_in[11];
    const float* Wtb  = (const float*)d_in[12];
    const float* btb  = (const float*)d_in[13];
    const float* Wout = (const float*)d_in[14];
    const float* bout = (const float*)d_in[15];
    float* out = (float*)d_out;

    // x-projection for all timesteps (time-parallel)
    precompute_xw_kernel<<<dim3(Bsz * Ssz / 64, BBsz / 64), 256>>>(x, Wb0, bb0);

    const float* Wb0h = Wb0 + Isz * BBsz;  // h-part of Wb0 (rows I..I+H)

    // persistent recurrent loop: one launch, 148 co-resident CTAs
    loop_kernel<<<NCTA, 256>>>(ts, Wb0h, Wbs, bbs,
                               Wff1, bff1, Wff2, bff2,
                               Wta, bta, Wtb, btb);

    final_kernel<<<dim3(Bsz / 64, Osz / 64), 256>>>(Wout, bout, out);
}

// round 6
// speedup vs baseline: 1.0512x; 1.0512x over previous
#include <cuda_runtime.h>

// Problem dims
#define Bsz 256   // batch
#define Ssz 512   // seq len
#define Isz 256   // input
#define Hsz 512   // hidden
#define BBsz 256  // backbone width
#define Osz 128   // output

#define NCTA 148  // B200 SM count; 1 CTA/SM in wave 1 -> co-resident
#define NTHR 512  // threads per CTA in the persistent loop

// Scratch (allocation-free: __device__ globals)
__device__ float g_xw[Ssz * Bsz * BBsz];     // [t][b][j] : x@Wb0_x + bb0
__device__ float g_h[Bsz * Hsz];             // hidden state
__device__ float g_z[Bsz * BBsz];            // z3 (last backbone activation)
__device__ float g_pA[8 * Bsz * BBsz];       // split-K partials (ping)
__device__ float g_pB[8 * Bsz * BBsz];       // split-K partials (pong)

// ---- fast grid barrier state (epoch-based, persistent across launches) ----
#define FLAG_STRIDE 32                        // 128 B between flags
__device__ unsigned g_arrive[NCTA * FLAG_STRIDE];
__device__ volatile unsigned g_release;
__device__ volatile unsigned g_epoch_base;    // continued across graph replays

__device__ __forceinline__ float fast_tanh(float x) {
    x = fminf(15.f, fmaxf(-15.f, x));
    float e = __expf(2.f * x);
    return (e - 1.f) / (e + 1.f);
}
__device__ __forceinline__ float fast_sigmoid(float x) {
    x = fminf(30.f, fmaxf(-30.f, x));
    return 1.f / (1.f + __expf(-x));
}

// Flag-based grid barrier. All CTAs resident. 'epoch' increments per call.
// Arrive: parallel STG of per-CTA flags. CTA0 polls all flags (1 thread per
// flag), then publishes release. Wrap-safe comparisons via signed subtract.
__device__ __forceinline__ void gsync(unsigned epoch) {
    __syncthreads();
    int tid = threadIdx.x;
    if (tid == 0) {
        __threadfence();                                      // release writes
        *(volatile unsigned*)&g_arrive[blockIdx.x * FLAG_STRIDE] = epoch;
    }
    if (blockIdx.x == 0) {
        if (tid < NCTA) {
            while ((int)(*(volatile unsigned*)&g_arrive[tid * FLAG_STRIDE] - epoch) < 0)
                __nanosleep(20);
        }
        __syncthreads();                  // all 148 flags observed
        if (tid == 0) {
            __threadfence();
            g_release = epoch;
        }
        __syncthreads();
        if (tid == 0) __threadfence();    // acquire side
    } else {
        if (tid == 0) {
            while ((int)(g_release - epoch) < 0) __nanosleep(20);
            __threadfence();                                  // acquire
        }
        __syncthreads();
    }
}

// 8-FMA micro-kernel over one 32-wide k-tile (2 rows x 4 cols per thread).
// As transposed [k][m], Bs [k][n]; rows padded to 68 floats (272 B, 16B-aligned).
__device__ __forceinline__ void gemm_ktile(const float (*As)[68], const float (*Bs)[68],
                                           float acc[2][4], int tx, int ty) {
    #pragma unroll
    for (int kk = 0; kk < 32; kk++) {
        float2 a = *(const float2*)&As[kk][ty * 2];
        float4 b = *(const float4*)&Bs[kk][tx * 4];
        acc[0][0] += a.x * b.x; acc[0][1] += a.x * b.y; acc[0][2] += a.x * b.z; acc[0][3] += a.x * b.w;
        acc[1][0] += a.y * b.x; acc[1][1] += a.y * b.y; acc[1][2] += a.y * b.z; acc[1][3] += a.y * b.w;
    }
}

// ---------------------------------------------------------------------------
// Stage A: partials of h @ Wb0h.  M=256,N=256,K=512, split-K8 (chunk 64).
// unit u in [0,128): ks=u&7, tile=u>>3 (4x4 tiles of 64x64). Out: g_pA.
// 512 threads: tx=tid&15 (n/4), ty=tid>>4 (0..31, m/2).
// ---------------------------------------------------------------------------
__device__ void stageA(int u, const float* __restrict__ Wb0h,
                       float (*As)[68], float (*Bs)[68]) {
    int ks = u & 7, tile = u >> 3;
    int m0 = (tile >> 2) * 64, n0 = (tile & 3) * 64;
    int tid = threadIdx.x;
    int tx = tid & 15, ty = tid >> 4;
    float acc[2][4] = {};

    for (int kt = 0; kt < 2; kt++) {
        int k0 = ks * 64 + kt * 32;
        {   // A-tile: 64m x 32k = 512 float4, 1 per thread, transposed store
            int m = tid >> 3, kg = (tid & 7) * 4;
            float4 v = *(const float4*)&g_h[(m0 + m) * Hsz + k0 + kg];
            As[kg + 0][m] = v.x; As[kg + 1][m] = v.y;
            As[kg + 2][m] = v.z; As[kg + 3][m] = v.w;
        }
        {   // B-tile: 32k x 64n = 512 float4, 1 per thread
            int k = tid >> 4, ng = (tid & 15) * 4;
            *(float4*)&Bs[k][ng] = *(const float4*)&Wb0h[(k0 + k) * BBsz + n0 + ng];
        }
        __syncthreads();
        gemm_ktile((const float(*)[68])As, (const float(*)[68])Bs, acc, tx, ty);
        __syncthreads();
    }
    #pragma unroll
    for (int i = 0; i < 2; i++) {
        int m = m0 + ty * 2 + i;
        float4 v = {acc[i][0], acc[i][1], acc[i][2], acc[i][3]};
        *(float4*)&g_pA[(ks * Bsz + m) * BBsz + n0 + tx * 4] = v;
    }
}

// ---------------------------------------------------------------------------
// Mid stage: prologue reduces split-K partials of previous layer (+base) and
// applies tanh to build the activated A-tile for its own K-chunk, then GEMM.
// unit u in [0,128): ks=u&7 (chunk of 32), tile=u>>3.  K total = 256.
// ---------------------------------------------------------------------------
__device__ void pmid(int u, const float* __restrict__ base, int base2d,
                     const float* __restrict__ W,
                     const float* __restrict__ pin, float* __restrict__ pout,
                     float (*As)[68], float (*Bs)[68]) {
    int ks = u & 7, tile = u >> 3;
    int m0 = (tile >> 2) * 64, n0 = (tile & 3) * 64;
    int k0 = ks * 32;
    int tid = threadIdx.x;
    int tx = tid & 15, ty = tid >> 4;

    {   // prologue: activated A-tile (reduce 8 partials + base, tanh)
        int m = tid >> 3, kg = (tid & 7) * 4;
        int gm = m0 + m, gk = k0 + kg;
        float4 v;
        if (base2d) v = *(const float4*)&base[gm * BBsz + gk];
        else        v = *(const float4*)&base[gk];
        #pragma unroll
        for (int p = 0; p < 8; p++) {
            float4 pv = *(const float4*)&pin[(p * Bsz + gm) * BBsz + gk];
            v.x += pv.x; v.y += pv.y; v.z += pv.z; v.w += pv.w;
        }
        As[kg + 0][m] = fast_tanh(v.x); As[kg + 1][m] = fast_tanh(v.y);
        As[kg + 2][m] = fast_tanh(v.z); As[kg + 3][m] = fast_tanh(v.w);
    }
    {
        int k = tid >> 4, ng = (tid & 15) * 4;
        *(float4*)&Bs[k][ng] = *(const float4*)&W[(k0 + k) * BBsz + n0 + ng];
    }
    __syncthreads();

    float acc[2][4] = {};
    gemm_ktile((const float(*)[68])As, (const float(*)[68])Bs, acc, tx, ty);
    __syncthreads();

    #pragma unroll
    for (int i = 0; i < 2; i++) {
        int m = m0 + ty * 2 + i;
        float4 v = {acc[i][0], acc[i][1], acc[i][2], acc[i][3]};
        *(float4*)&pout[(ks * Bsz + m) * BBsz + n0 + tx * 4] = v;
    }
}

// ---------------------------------------------------------------------------
// r4: g_z = tanh(bias + sum_8 pin)   (16384 float4, all CTAs)
// ---------------------------------------------------------------------------
__device__ void r4(const float* __restrict__ bias, const float* __restrict__ pin) {
    int tid0 = blockIdx.x * NTHR + threadIdx.x;
    for (int s = tid0; s < (Bsz * BBsz / 4); s += gridDim.x * NTHR) {
        int idx = s * 4;
        float4 v = *(const float4*)&bias[idx & (BBsz - 1)];
        #pragma unroll
        for (int p = 0; p < 8; p++) {
            float4 pv = *(const float4*)&pin[p * Bsz * BBsz + idx];
            v.x += pv.x; v.y += pv.y; v.z += pv.z; v.w += pv.w;
        }
        float4 o = {fast_tanh(v.x), fast_tanh(v.y), fast_tanh(v.z), fast_tanh(v.w)};
        *(float4*)&g_z[idx] = o;
    }
}

// ---------------------------------------------------------------------------
// Heads: fused 4-head GEMM (64 batch x 16 hcol x 4 heads, K=256) + CfC gate.
// unit u in [0,128): m0=(u>>5)*64, h0=(u&31)*16. Writes g_h.
// Weights interleaved in smem: Bs[k][hcol*4 + head] -> inner loop one LDS.128.
// ---------------------------------------------------------------------------
__device__ void heads(int u, int t,
                      const float* __restrict__ Wff1, const float* __restrict__ Wff2,
                      const float* __restrict__ Wta,  const float* __restrict__ Wtb,
                      const float* __restrict__ bff1, const float* __restrict__ bff2,
                      const float* __restrict__ bta,  const float* __restrict__ btb,
                      const float* __restrict__ ts,
                      float (*As)[68], float (*Bs)[68]) {
    int m0 = (u >> 5) * 64;
    int h0 = (u & 31) * 16;
    int tid = threadIdx.x;
    int tx = tid & 15, ty = tid >> 4;
    float acc[2][4] = {};

    for (int k0 = 0; k0 < BBsz; k0 += 32) {
        {   // A-tile from g_z
            int m = tid >> 3, kg = (tid & 7) * 4;
            float4 v = *(const float4*)&g_z[(m0 + m) * BBsz + k0 + kg];
            As[kg + 0][m] = v.x; As[kg + 1][m] = v.y;
            As[kg + 2][m] = v.z; As[kg + 3][m] = v.w;
        }
        {   // weights, interleaved 4 heads per hcol: one float4 STS per thread
            int k = tid >> 4, hc = tid & 15;
            int gidx = (k0 + k) * Hsz + h0 + hc;
            float4 w = {Wff1[gidx], Wff2[gidx], Wta[gidx], Wtb[gidx]};
            *(float4*)&Bs[k][hc * 4] = w;
        }
        __syncthreads();
        gemm_ktile((const float(*)[68])As, (const float(*)[68])Bs, acc, tx, ty);
        __syncthreads();
    }
    int hcol = h0 + tx;
    float bf1 = bff1[hcol], bf2 = bff2[hcol], ba = bta[hcol], bb = btb[hcol];
    #pragma unroll
    for (int i = 0; i < 2; i++) {
        int b = m0 + ty * 2 + i;
        float tsv = ts[b * Ssz + t];
        float f1 = fast_tanh(acc[i][0] + bf1);
        float f2 = fast_tanh(acc[i][1] + bf2);
        float ti = fast_sigmoid((acc[i][2] + ba) * tsv + (acc[i][3] + bb));
        g_h[b * Hsz + hcol] = f1 * (1.f - ti) + ti * f2;
    }
}

// ---------------------------------------------------------------------------
// The persistent time loop: one kernel, flag-based software grid barriers.
// ---------------------------------------------------------------------------
__global__ void __launch_bounds__(NTHR, 1)
loop_kernel(const float* __restrict__ ts,
            const float* __restrict__ Wb0h,
            const float* __restrict__ Wbs, const float* __restrict__ bbs,
            const float* __restrict__ Wff1, const float* __restrict__ bff1,
            const float* __restrict__ Wff2, const float* __restrict__ bff2,
            const float* __restrict__ Wta,  const float* __restrict__ bta,
            const float* __restrict__ Wtb,  const float* __restrict__ btb) {
    __shared__ __align__(16) float As[32][68];
    __shared__ __align__(16) float Bs[32][68];
    int bid = blockIdx.x;

    // epoch base persisted across launches (CTA0 updates it at the end; no CTA
    // can be past the last barrier of the PREVIOUS launch when we read here).
    unsigned epoch = g_epoch_base;

    // zero hidden state
    for (int s = bid * NTHR + threadIdx.x; s < Bsz * Hsz / 4; s += gridDim.x * NTHR) {
        float4 z = {0.f, 0.f, 0.f, 0.f};
        *(float4*)&g_h[s * 4] = z;
    }
    gsync(++epoch);

    for (int t = 0; t < Ssz; t++) {
        if (bid < 128) stageA(bid, Wb0h, As, Bs);
        gsync(++epoch);
        if (bid < 128) pmid(bid, g_xw + (size_t)t * Bsz * BBsz, 1,
                            Wbs, g_pA, g_pB, As, Bs);
        gsync(++epoch);
        if (bid < 128) pmid(bid, bbs + 0 * BBsz, 0,
                            Wbs + 1 * BBsz * BBsz, g_pB, g_pA, As, Bs);
        gsync(++epoch);
        if (bid < 128) pmid(bid, bbs + 1 * BBsz, 0,
                            Wbs + 2 * BBsz * BBsz, g_pA, g_pB, As, Bs);
        gsync(++epoch);
        r4(bbs + 2 * BBsz, g_pB);
        gsync(++epoch);
        if (bid < 128) heads(bid, t, Wff1, Wff2, Wta, Wtb,
                             bff1, bff2, bta, btb, ts, As, Bs);
        gsync(++epoch);
    }

    // publish epoch base for the next launch (graph replay)
    if (bid == 0 && threadIdx.x == 0) g_epoch_base = epoch;
}

// ---------------------------------------------------------------------------
// Precompute g_xw[t][b][:] = bb0 + x[b][t][:] @ Wb0[0:I][:]  (time-parallel)
// 256 threads, 4x4 blocking (already ~94% of FFMA ceiling).
// ---------------------------------------------------------------------------
__global__ void precompute_xw_kernel(const float* __restrict__ x,
                                     const float* __restrict__ Wb0,
                                     const float* __restrict__ bb0) {
    __shared__ __align__(16) float As[32][68];
    __shared__ __align__(16) float Bs[32][68];
    int m0 = blockIdx.x * 64;
    int n0 = blockIdx.y * 64;
    int tid = threadIdx.x;
    int tx = tid & 15, ty = tid >> 4;
    float acc[4][4] = {};

    for (int k0 = 0; k0 < Isz; k0 += 32) {
        #pragma unroll
        for (int s = tid; s < 512; s += 256) {
            int m = s >> 3, kg = (s & 7) * 4;
            float4 v = *(const float4*)&x[(m0 + m) * Isz + k0 + kg];
            As[kg + 0][m] = v.x; As[kg + 1][m] = v.y;
            As[kg + 2][m] = v.z; As[kg + 3][m] = v.w;
        }
        #pragma unroll
        for (int s = tid; s < 512; s += 256) {
            int k = s >> 4, ng = (s & 15) * 4;
            *(float4*)&Bs[k][ng] = *(const float4*)&Wb0[(k0 + k) * BBsz + n0 + ng];
        }
        __syncthreads();
        #pragma unroll
        for (int kk = 0; kk < 32; kk++) {
            float4 a = *(const float4*)&As[kk][ty * 4];
            float4 b = *(const float4*)&Bs[kk][tx * 4];
            acc[0][0] += a.x * b.x; acc[0][1] += a.x * b.y; acc[0][2] += a.x * b.z; acc[0][3] += a.x * b.w;
            acc[1][0] += a.y * b.x; acc[1][1] += a.y * b.y; acc[1][2] += a.y * b.z; acc[1][3] += a.y * b.w;
            acc[2][0] += a.z * b.x; acc[2][1] += a.z * b.y; acc[2][2] += a.z * b.z; acc[2][3] += a.z * b.w;
            acc[3][0] += a.w * b.x; acc[3][1] += a.w * b.y; acc[3][2] += a.w * b.z; acc[3][3] += a.w * b.w;
        }
        __syncthreads();
    }
    float4 bias = *(const float4*)&bb0[n0 + tx * 4];
    #pragma unroll
    for (int i = 0; i < 4; i++) {
        int m = m0 + ty * 4 + i;       // m = b*S + t
        int t = m & (Ssz - 1);
        int b = m >> 9;
        float4 v = {acc[i][0] + bias.x, acc[i][1] + bias.y,
                    acc[i][2] + bias.z, acc[i][3] + bias.w};
        *(float4*)&g_xw[((size_t)t * Bsz + b) * BBsz + n0 + tx * 4] = v;
    }
}

// ---------------------------------------------------------------------------
// Final: out = h @ W_out + b_out   (256 x 128, K=512)
// ---------------------------------------------------------------------------
__global__ void final_kernel(const float* __restrict__ Wout,
                             const float* __restrict__ bout,
                             float* __restrict__ out) {
    __shared__ __align__(16) float As[32][68];
    __shared__ __align__(16) float Bs[32][68];
    int m0 = blockIdx.x * 64;
    int n0 = blockIdx.y * 64;
    int tid = threadIdx.x;
    int tx = tid & 15, ty = tid >> 4;
    float acc[4][4] = {};

    for (int k0 = 0; k0 < Hsz; k0 += 32) {
        #pragma unroll
        for (int s = tid; s < 512; s += 256) {
            int m = s >> 3, kg = (s & 7) * 4;
            float4 v = *(const float4*)&g_h[(m0 + m) * Hsz + k0 + kg];
            As[kg + 0][m] = v.x; As[kg + 1][m] = v.y;
            As[kg + 2][m] = v.z; As[kg + 3][m] = v.w;
        }
        #pragma unroll
        for (int s = tid; s < 512; s += 256) {
            int k = s >> 4, ng = (s & 15) * 4;
            *(float4*)&Bs[k][ng] = *(const float4*)&Wout[(k0 + k) * Osz + n0 + ng];
        }
        __syncthreads();
        #pragma unroll
        for (int kk = 0; kk < 32; kk++) {
            float4 a = *(const float4*)&As[kk][ty * 4];
            float4 b = *(const float4*)&Bs[kk][tx * 4];
            acc[0][0] += a.x * b.x; acc[0][1] += a.x * b.y; acc[0][2] += a.x * b.z; acc[0][3] += a.x * b.w;
            acc[1][0] += a.y * b.x; acc[1][1] += a.y * b.y; acc[1][2] += a.y * b.z; acc[1][3] += a.y * b.w;
            acc[2][0] += a.z * b.x; acc[2][1] += a.z * b.y; acc[2][2] += a.z * b.z; acc[2][3] += a.z * b.w;
            acc[3][0] += a.w * b.x; acc[3][1] += a.w * b.y; acc[3][2] += a.w * b.z; acc[3][3] += a.w * b.w;
        }
        __syncthreads();
    }
    float4 bias = *(const float4*)&bout[n0 + tx * 4];
    #pragma unroll
    for (int i = 0; i < 4; i++) {
        int m = m0 + ty * 4 + i;
        float4 v = {acc[i][0] + bias.x, acc[i][1] + bias.y,
                    acc[i][2] + bias.z, acc[i][3] + bias.w};
        *(float4*)&out[m * Osz + n0 + tx * 4] = v;
    }
}

// ---------------------------------------------------------------------------
// Host launcher: 3 graph nodes total.
// ---------------------------------------------------------------------------
extern "C" void kernel_launch(void* const* d_in, const int* in_sizes, int n_in,
                              void* d_out, int out_size) {
    const float* x    = (const float*)d_in[0];
    const float* ts   = (const float*)d_in[1];
    const float* Wb0  = (const float*)d_in[2];
    const float* bb0  = (const float*)d_in[3];
    const float* Wbs  = (const float*)d_in[4];   // (3, 256, 256)
    const float* bbs  = (const float*)d_in[5];   // (3, 256)
    const float* Wff1 = (const float*)d_in[6];
    const float* bff1 = (const float*)d_in[7];
    const float* Wff2 = (const float*)d_in[8];
    const float* bff2 = (const float*)d_in[9];
    const float* Wta  = (const float*)d_in[10];
    const float* bta  = (const float*)d_in[11];
    const float* Wtb  = (const float*)d_in[12];
    const float* btb  = (const float*)d_in[13];
    const float* Wout = (const float*)d_in[14];
    const float* bout = (const float*)d_in[15];
    float* out = (float*)d_out;

    // x-projection for all timesteps (time-parallel)
    precompute_xw_kernel<<<dim3(Bsz * Ssz / 64, BBsz / 64), 256>>>(x, Wb0, bb0);

    const float* Wb0h = Wb0 + Isz * BBsz;  // h-part of Wb0 (rows I..I+H)

    // persistent recurrent loop: one launch, 148 co-resident CTAs
    loop_kernel<<<NCTA, NTHR>>>(ts, Wb0h, Wbs, bbs,
                                Wff1, bff1, Wff2, bff2,
                                Wta, bta, Wtb, btb);

    final_kernel<<<dim3(Bsz / 64, Osz / 64), 256>>>(Wout, bout, out);
}